// round 1
// baseline (speedup 1.0000x reference)
#include <cuda_runtime.h>

// Problem constants
#define B_    2
#define T_    2048
#define C_    1024
#define NH_   16
#define HD_   64
#define M_    (B_ * T_)     // 4096 rows
#define NQKV_ (3 * C_)      // 3072

// Scratch (device globals: allocation-free)
__device__ float g_qkv[(size_t)M_ * NQKV_];   // (B*T, 3C)
__device__ float g_att[(size_t)M_ * C_];      // (B*T, C) attention output

// ---------------------------------------------------------------------------
// SGEMM + bias: C[M,N] = A[M,K] @ B[K,N] + bias[N]
// 128x128x16 tiles, 256 threads, 8x8 microtile (1 B LDS per lane-FMA: balanced
// against the 128B/cyc smem crossbar vs 128 FMA/cyc/SM fp32 pipe).
// ---------------------------------------------------------------------------
__global__ __launch_bounds__(256, 2)
void sgemm_bias(const float* __restrict__ A, const float* __restrict__ Bm,
                const float* __restrict__ bias, float* __restrict__ Cm,
                int M, int N, int K) {
    __shared__ __align__(16) float As[16][132];   // A^T tile: [k][m], pad 4
    __shared__ __align__(16) float Bs[16][128];   // B tile:   [k][n]

    const int tid = threadIdx.x;
    const int tx  = tid & 15;    // 0..15 -> n microtile
    const int ty  = tid >> 4;    // 0..15 -> m microtile
    const int row0 = blockIdx.y * 128;
    const int col0 = blockIdx.x * 128;

    float acc[8][8];
#pragma unroll
    for (int i = 0; i < 8; i++)
#pragma unroll
        for (int j = 0; j < 8; j++) acc[i][j] = 0.f;

    for (int k0 = 0; k0 < K; k0 += 16) {
        // Load A tile (128 rows x 16 cols) as float4, store transposed.
#pragma unroll
        for (int t = tid; t < 512; t += 256) {
            int r  = t >> 2;           // 0..127
            int kc = (t & 3) << 2;     // 0,4,8,12
            float4 v = *reinterpret_cast<const float4*>(
                &A[(size_t)(row0 + r) * K + k0 + kc]);
            As[kc + 0][r] = v.x;
            As[kc + 1][r] = v.y;
            As[kc + 2][r] = v.z;
            As[kc + 3][r] = v.w;
        }
        // Load B tile (16 rows x 128 cols) as float4.
#pragma unroll
        for (int t = tid; t < 512; t += 256) {
            int r  = t >> 5;           // 0..15
            int c4 = (t & 31) << 2;    // 0..124
            *reinterpret_cast<float4*>(&Bs[r][c4]) =
                *reinterpret_cast<const float4*>(
                    &Bm[(size_t)(k0 + r) * N + col0 + c4]);
        }
        __syncthreads();

#pragma unroll
        for (int kk = 0; kk < 16; kk++) {
            float a[8], b[8];
            *reinterpret_cast<float4*>(a)     = *reinterpret_cast<const float4*>(&As[kk][ty * 8]);
            *reinterpret_cast<float4*>(a + 4) = *reinterpret_cast<const float4*>(&As[kk][ty * 8 + 4]);
            *reinterpret_cast<float4*>(b)     = *reinterpret_cast<const float4*>(&Bs[kk][tx * 8]);
            *reinterpret_cast<float4*>(b + 4) = *reinterpret_cast<const float4*>(&Bs[kk][tx * 8 + 4]);
#pragma unroll
            for (int i = 0; i < 8; i++)
#pragma unroll
                for (int j = 0; j < 8; j++)
                    acc[i][j] += a[i] * b[j];
        }
        __syncthreads();
    }

    // Epilogue with bias
#pragma unroll
    for (int i = 0; i < 8; i++) {
        const size_t r = (size_t)(row0 + ty * 8 + i);
#pragma unroll
        for (int j = 0; j < 8; j += 4) {
            const int c = col0 + tx * 8 + j;
            float4 v;
            v.x = acc[i][j + 0] + bias[c + 0];
            v.y = acc[i][j + 1] + bias[c + 1];
            v.z = acc[i][j + 2] + bias[c + 2];
            v.w = acc[i][j + 3] + bias[c + 3];
            *reinterpret_cast<float4*>(&Cm[r * N + c]) = v;
        }
    }
}

// ---------------------------------------------------------------------------
// Flash attention (fp32, causal). One block = one (b,h) x 64-query tile.
// 128 threads: ty(0..7) owns 8 queries, tx(0..15) owns 4 kv cols / 4 out dims.
// Online softmax with 16-lane shfl reductions. Causal early exit (kvb <= qb).
// Dynamic smem: Qt, Kt (d-major), Vs, Ps, each 64x68 floats = 69632 B.
// ---------------------------------------------------------------------------
#define AT_S 68   // padded row stride (keeps float4 alignment, dodges conflicts)

__global__ __launch_bounds__(128)
void attn_kernel(const float* __restrict__ qkv, float* __restrict__ att) {
    extern __shared__ __align__(16) float sm[];
    float* Qt = sm;                 // [d][q]  (transposed), scaled by 1/sqrt(HD)
    float* Kt = sm + 64 * AT_S;     // [d][j]  (transposed)
    float* Vs = sm + 2 * 64 * AT_S; // [j][d]  row-major
    float* Ps = sm + 3 * 64 * AT_S; // [q][j]  row-major

    const int tid = threadIdx.x;
    const int tx  = tid & 15;
    const int ty  = tid >> 4;
    const int qb  = blockIdx.x;          // 0..31 query tile
    const int bh  = blockIdx.y;          // 0..31
    const int b   = bh >> 4, h = bh & 15;

    const float* qbase = qkv + (size_t)b * T_ * NQKV_ + h * HD_;
    const float* kbase = qbase + C_;
    const float* vbase = qbase + 2 * C_;

    // Load Q tile (pre-scaled by 1/sqrt(64) = 0.125), store d-major.
    for (int idx = tid; idx < 64 * 64; idx += 128) {
        int r = idx >> 6, d = idx & 63;
        Qt[d * AT_S + r] = qbase[(size_t)(qb * 64 + r) * NQKV_ + d] * 0.125f;
    }

    float acc[8][4];
    float m[8], l[8];
#pragma unroll
    for (int i = 0; i < 8; i++) {
        m[i] = -1e30f; l[i] = 0.f;
#pragma unroll
        for (int j = 0; j < 4; j++) acc[i][j] = 0.f;
    }

    for (int kvb = 0; kvb <= qb; kvb++) {
        __syncthreads();   // protect Kt/Vs/Ps from previous iteration readers
        for (int idx = tid; idx < 64 * 64; idx += 128) {
            int r = idx >> 6, d = idx & 63;
            size_t goff = (size_t)(kvb * 64 + r) * NQKV_ + d;
            Kt[d * AT_S + r] = kbase[goff];
            Vs[r * AT_S + d] = vbase[goff];
        }
        __syncthreads();

        // S = (Q * scale) @ K^T  -> s[8][4]
        float s[8][4];
#pragma unroll
        for (int i = 0; i < 8; i++)
#pragma unroll
            for (int j = 0; j < 4; j++) s[i][j] = 0.f;

#pragma unroll 4
        for (int d = 0; d < 64; d++) {
            float4 kf = *reinterpret_cast<const float4*>(&Kt[d * AT_S + tx * 4]);
#pragma unroll
            for (int i = 0; i < 8; i++) {
                float qf = Qt[d * AT_S + ty * 8 + i];
                s[i][0] += qf * kf.x;
                s[i][1] += qf * kf.y;
                s[i][2] += qf * kf.z;
                s[i][3] += qf * kf.w;
            }
        }

        if (kvb == qb) {   // diagonal tile: causal mask (local indices suffice)
#pragma unroll
            for (int i = 0; i < 8; i++)
#pragma unroll
                for (int j = 0; j < 4; j++)
                    if (tx * 4 + j > ty * 8 + i) s[i][j] = -1e30f;
        }

        // Online softmax (row groups = 16 lanes sharing ty)
#pragma unroll
        for (int i = 0; i < 8; i++) {
            float mx = fmaxf(fmaxf(s[i][0], s[i][1]), fmaxf(s[i][2], s[i][3]));
            mx = fmaxf(mx, __shfl_xor_sync(0xffffffffu, mx, 1));
            mx = fmaxf(mx, __shfl_xor_sync(0xffffffffu, mx, 2));
            mx = fmaxf(mx, __shfl_xor_sync(0xffffffffu, mx, 4));
            mx = fmaxf(mx, __shfl_xor_sync(0xffffffffu, mx, 8));
            float mnew  = fmaxf(m[i], mx);
            float alpha = __expf(m[i] - mnew);
            float p0 = __expf(s[i][0] - mnew);
            float p1 = __expf(s[i][1] - mnew);
            float p2 = __expf(s[i][2] - mnew);
            float p3 = __expf(s[i][3] - mnew);
            float ls = p0 + p1 + p2 + p3;
            ls += __shfl_xor_sync(0xffffffffu, ls, 1);
            ls += __shfl_xor_sync(0xffffffffu, ls, 2);
            ls += __shfl_xor_sync(0xffffffffu, ls, 4);
            ls += __shfl_xor_sync(0xffffffffu, ls, 8);
            l[i] = l[i] * alpha + ls;
            m[i] = mnew;
#pragma unroll
            for (int j = 0; j < 4; j++) acc[i][j] *= alpha;
            float4 pv = make_float4(p0, p1, p2, p3);
            *reinterpret_cast<float4*>(&Ps[(ty * 8 + i) * AT_S + tx * 4]) = pv;
        }
        __syncthreads();   // Ps complete before PV

        // O += P @ V
#pragma unroll 2
        for (int j4 = 0; j4 < 64; j4 += 4) {
            float4 v0 = *reinterpret_cast<const float4*>(&Vs[(j4 + 0) * AT_S + tx * 4]);
            float4 v1 = *reinterpret_cast<const float4*>(&Vs[(j4 + 1) * AT_S + tx * 4]);
            float4 v2 = *reinterpret_cast<const float4*>(&Vs[(j4 + 2) * AT_S + tx * 4]);
            float4 v3 = *reinterpret_cast<const float4*>(&Vs[(j4 + 3) * AT_S + tx * 4]);
#pragma unroll
            for (int i = 0; i < 8; i++) {
                float4 p = *reinterpret_cast<const float4*>(&Ps[(ty * 8 + i) * AT_S + j4]);
                acc[i][0] += p.x * v0.x + p.y * v1.x + p.z * v2.x + p.w * v3.x;
                acc[i][1] += p.x * v0.y + p.y * v1.y + p.z * v2.y + p.w * v3.y;
                acc[i][2] += p.x * v0.z + p.y * v1.z + p.z * v2.z + p.w * v3.z;
                acc[i][3] += p.x * v0.w + p.y * v1.w + p.z * v2.w + p.w * v3.w;
            }
        }
    }

    // Epilogue: normalize and scatter to (B*T, C) at this head's column slice.
#pragma unroll
    for (int i = 0; i < 8; i++) {
        float inv = 1.f / l[i];
        float4 o = make_float4(acc[i][0] * inv, acc[i][1] * inv,
                               acc[i][2] * inv, acc[i][3] * inv);
        size_t row = (size_t)b * T_ + qb * 64 + ty * 8 + i;
        *reinterpret_cast<float4*>(&att[row * C_ + h * HD_ + tx * 4]) = o;
    }
}

// ---------------------------------------------------------------------------
// Launch
// ---------------------------------------------------------------------------
extern "C" void kernel_launch(void* const* d_in, const int* in_sizes, int n_in,
                              void* d_out, int out_size) {
    const float* x     = (const float*)d_in[0];
    const float* Wqkv  = (const float*)d_in[1];
    const float* bqkv  = (const float*)d_in[2];
    const float* Wproj = (const float*)d_in[3];
    const float* bproj = (const float*)d_in[4];
    float* out = (float*)d_out;

    float *qkv_ptr, *att_ptr;
    cudaGetSymbolAddress((void**)&qkv_ptr, g_qkv);
    cudaGetSymbolAddress((void**)&att_ptr, g_att);

    const int attn_smem = 4 * 64 * AT_S * sizeof(float);  // 69632 B
    cudaFuncSetAttribute(attn_kernel,
                         cudaFuncAttributeMaxDynamicSharedMemorySize, attn_smem);

    // 1) QKV GEMM: (4096 x 1024) @ (1024 x 3072) + bqkv
    dim3 g1(NQKV_ / 128, M_ / 128);   // 24 x 32
    sgemm_bias<<<g1, 256>>>(x, Wqkv, bqkv, qkv_ptr, M_, NQKV_, C_);

    // 2) Causal flash attention over the interleaved qkv buffer
    dim3 g2(T_ / 64, B_ * NH_);       // 32 x 32
    attn_kernel<<<g2, 128, attn_smem>>>(qkv_ptr, att_ptr);

    // 3) Output projection: (4096 x 1024) @ (1024 x 1024) + bproj
    dim3 g3(C_ / 128, M_ / 128);      // 8 x 32
    sgemm_bias<<<g3, 256>>>(att_ptr, Wproj, bproj, out, M_, C_, C_);
}